// round 1
// baseline (speedup 1.0000x reference)
#include <cuda_runtime.h>
#include <math.h>

#define NHEADS 12
#define DH     64
#define LW     49
#define WSZ    7
#define CCH    768
#define NWIN   2048                 // 32 * 8 * 8 windows
#define MROWS  (NWIN * LW)          // 100352

// 308 MB scratch for the concat-head attention output (N, L, C)
__device__ float g_scratch[(size_t)NWIN * LW * CCH];

// ---------------- shared memory layout for the attention kernel (floats) ----
#define XS_STRIDE 68
#define WT_STRIDE 68
#define QS_STRIDE 68
#define KT_STRIDE 56
#define VS_STRIDE 68
#define PS_STRIDE 52

#define XS_OFF 0
#define WT_OFF (XS_OFF + 50 * XS_STRIDE)            // 3400
#define QS_OFF (WT_OFF + 64 * WT_STRIDE)            // +4352
#define KT_OFF (QS_OFF + 50 * QS_STRIDE)            // +3400
#define VS_OFF (KT_OFF + 64 * KT_STRIDE)            // +3584
#define PS_OFF (VS_OFF + 50 * VS_STRIDE)            // +3400
#define SMEM_FLOATS (PS_OFF + 50 * PS_STRIDE)       // 20736 floats
#define SMEM_BYTES (SMEM_FLOATS * 4)                // 82944 B

// ============================================================================
// Kernel A: per-(window, head) fused QKV projection + attention.
// grid = NWIN*NHEADS blocks, 128 threads.
// ============================================================================
__global__ void __launch_bounds__(128, 2)
attn_kernel(const float* __restrict__ x,
            const float* __restrict__ Wq,
            const float* __restrict__ Wk,
            const float* __restrict__ Wv)
{
    extern __shared__ float sm[];
    float* xs = sm + XS_OFF;   // [50][68]  x window slice (row 49 = pad)
    float* Wt = sm + WT_OFF;   // [64][68]  W transposed: Wt[d][e]
    float* Qs = sm + QS_OFF;   // [50][68]  Q, row-major (l, e)
    float* Kt = sm + KT_OFF;   // [64][56]  K transposed: Kt[e][m]
    float* Vs = sm + VS_OFF;   // [50][68]  V, row-major (m, d)
    float* Ps = sm + PS_OFF;   // [50][52]  scores / probs

    const int tid = threadIdx.x;
    const int h = blockIdx.x % NHEADS;
    const int n = blockIdx.x / NHEADS;
    const int b  = n >> 6;
    const int hb = (n >> 3) & 7;
    const int wb = n & 7;

    // ---- load x window slice for this head: xs[l][d] ----
    for (int idx = tid; idx < LW * DH; idx += 128) {
        int l = idx >> 6, d = idx & 63;
        int i = l / 7, j = l - i * 7;
        int r = hb * WSZ + i;
        int c = wb * WSZ + j;
        xs[l * XS_STRIDE + d] = x[(((size_t)b * 56 + r) * 56 + c) * CCH + h * DH + d];
    }
    // zero the pad rows so the 2-row tiles read benign values
    for (int d = tid; d < XS_STRIDE; d += 128) {
        xs[49 * XS_STRIDE + d] = 0.f;
        Qs[49 * QS_STRIDE + d] = 0.f;
    }
    for (int d = tid; d < PS_STRIDE; d += 128) Ps[49 * PS_STRIDE + d] = 0.f;

    // ---- three projections: p=0 -> Q, p=1 -> K (transposed), p=2 -> V ----
    const float* Wsrc[3] = {Wq + h * DH * DH, Wk + h * DH * DH, Wv + h * DH * DH};
    for (int p = 0; p < 3; ++p) {
        __syncthreads();
        const float* W = Wsrc[p];
        for (int idx = tid; idx < DH * DH; idx += 128) {
            int e = idx >> 6, d = idx & 63;
            Wt[d * WT_STRIDE + e] = W[idx];   // transpose into smem
        }
        __syncthreads();
        // 25 l-tiles (2 rows) x 8 e-tiles (8 cols) = 200 items
        for (int it = tid; it < 200; it += 128) {
            int lt = it >> 3, et = it & 7;
            int l0 = lt * 2, e0 = et * 8;
            bool two = (l0 + 1 < LW);
            float acc0[8], acc1[8];
            #pragma unroll
            for (int j = 0; j < 8; ++j) { acc0[j] = 0.f; acc1[j] = 0.f; }
            #pragma unroll 8
            for (int d = 0; d < DH; ++d) {
                float x0 = xs[l0 * XS_STRIDE + d];
                float x1 = xs[(l0 + 1) * XS_STRIDE + d];
                float4 wA = *(const float4*)&Wt[d * WT_STRIDE + e0];
                float4 wB = *(const float4*)&Wt[d * WT_STRIDE + e0 + 4];
                float wv[8] = {wA.x, wA.y, wA.z, wA.w, wB.x, wB.y, wB.z, wB.w};
                #pragma unroll
                for (int j = 0; j < 8; ++j) {
                    acc0[j] += x0 * wv[j];
                    acc1[j] += x1 * wv[j];
                }
            }
            if (p == 1) {
                // store K transposed: Kt[e][m]
                #pragma unroll
                for (int j = 0; j < 8; ++j) {
                    Kt[(e0 + j) * KT_STRIDE + l0] = acc0[j];
                    if (two) Kt[(e0 + j) * KT_STRIDE + l0 + 1] = acc1[j];
                }
            } else {
                float* Out = (p == 0) ? Qs : Vs;
                int stride = (p == 0) ? QS_STRIDE : VS_STRIDE;
                *(float4*)&Out[l0 * stride + e0]     = make_float4(acc0[0], acc0[1], acc0[2], acc0[3]);
                *(float4*)&Out[l0 * stride + e0 + 4] = make_float4(acc0[4], acc0[5], acc0[6], acc0[7]);
                if (two) {
                    *(float4*)&Out[(l0 + 1) * stride + e0]     = make_float4(acc1[0], acc1[1], acc1[2], acc1[3]);
                    *(float4*)&Out[(l0 + 1) * stride + e0 + 4] = make_float4(acc1[4], acc1[5], acc1[6], acc1[7]);
                }
            }
        }
    }
    __syncthreads();

    // ---- scores = Q @ K^T / 8 : 25 l-tiles x 7 m-tiles = 175 items ----
    for (int it = tid; it < 175; it += 128) {
        int lt = it / 7, mt = it - (it / 7) * 7;
        int l0 = lt * 2, m0 = mt * 8;
        float acc0[8], acc1[8];
        #pragma unroll
        for (int j = 0; j < 8; ++j) { acc0[j] = 0.f; acc1[j] = 0.f; }
        #pragma unroll 8
        for (int e = 0; e < DH; ++e) {
            float q0 = Qs[l0 * QS_STRIDE + e];
            float q1 = Qs[(l0 + 1) * QS_STRIDE + e];
            float4 kA = *(const float4*)&Kt[e * KT_STRIDE + m0];
            float4 kB = *(const float4*)&Kt[e * KT_STRIDE + m0 + 4];
            float kv[8] = {kA.x, kA.y, kA.z, kA.w, kB.x, kB.y, kB.z, kB.w};
            #pragma unroll
            for (int j = 0; j < 8; ++j) {
                acc0[j] += q0 * kv[j];
                acc1[j] += q1 * kv[j];
            }
        }
        int mlim = LW - m0; if (mlim > 8) mlim = 8;
        bool two = (l0 + 1 < LW);
        for (int j = 0; j < mlim; ++j) {
            Ps[l0 * PS_STRIDE + m0 + j] = acc0[j] * 0.125f;
            if (two) Ps[(l0 + 1) * PS_STRIDE + m0 + j] = acc1[j] * 0.125f;
        }
    }
    __syncthreads();

    // ---- softmax: one thread per row ----
    if (tid < LW) {
        float* row = &Ps[tid * PS_STRIDE];
        float mx = -1e30f;
        #pragma unroll
        for (int m = 0; m < LW; ++m) mx = fmaxf(mx, row[m]);
        float s = 0.f;
        #pragma unroll
        for (int m = 0; m < LW; ++m) { float e = __expf(row[m] - mx); row[m] = e; s += e; }
        float inv = 1.f / s;
        #pragma unroll
        for (int m = 0; m < LW; ++m) row[m] *= inv;
    }
    __syncthreads();

    // ---- out = P @ V -> scratch[(n*49+l)*768 + h*64 + d] ----
    for (int it = tid; it < 200; it += 128) {
        int lt = it >> 3, dt = it & 7;
        int l0 = lt * 2, d0 = dt * 8;
        bool two = (l0 + 1 < LW);
        float acc0[8], acc1[8];
        #pragma unroll
        for (int j = 0; j < 8; ++j) { acc0[j] = 0.f; acc1[j] = 0.f; }
        #pragma unroll 7
        for (int m = 0; m < LW; ++m) {
            float p0 = Ps[l0 * PS_STRIDE + m];
            float p1 = Ps[(l0 + 1) * PS_STRIDE + m];
            float4 vA = *(const float4*)&Vs[m * VS_STRIDE + d0];
            float4 vB = *(const float4*)&Vs[m * VS_STRIDE + d0 + 4];
            float vv[8] = {vA.x, vA.y, vA.z, vA.w, vB.x, vB.y, vB.z, vB.w};
            #pragma unroll
            for (int j = 0; j < 8; ++j) {
                acc0[j] += p0 * vv[j];
                acc1[j] += p1 * vv[j];
            }
        }
        float* dst = &g_scratch[((size_t)n * LW + l0) * CCH + h * DH + d0];
        *(float4*)&dst[0] = make_float4(acc0[0], acc0[1], acc0[2], acc0[3]);
        *(float4*)&dst[4] = make_float4(acc0[4], acc0[5], acc0[6], acc0[7]);
        if (two) {
            *(float4*)&dst[CCH]     = make_float4(acc1[0], acc1[1], acc1[2], acc1[3]);
            *(float4*)&dst[CCH + 4] = make_float4(acc1[4], acc1[5], acc1[6], acc1[7]);
        }
    }
}

// ============================================================================
// Kernel B: y[M,768] = S[M,768] @ Wo^T + bo.  SGEMM 128x64x16, 256 threads,
// 8x4 register tile per thread.
// ============================================================================
#define BM 128
#define BN 64
#define BK 16

__global__ void __launch_bounds__(256)
proj_kernel(const float* __restrict__ Wo,
            const float* __restrict__ bo,
            float* __restrict__ y)
{
    __shared__ float As[BK][BM];
    __shared__ float Bs[BK][BN];

    const int tid = threadIdx.x;
    const int tx = tid & 15;   // N direction (4 cols each)
    const int ty = tid >> 4;   // M direction (8 rows each)
    const int m_base = blockIdx.y * BM;
    const int n_base = blockIdx.x * BN;
    const float* S = g_scratch;

    float acc[8][4];
    #pragma unroll
    for (int i = 0; i < 8; ++i)
        #pragma unroll
        for (int j = 0; j < 4; ++j) acc[i][j] = 0.f;

    for (int kt = 0; kt < CCH; kt += BK) {
        // load A tile (128x16), transposed into As[k][m]
        #pragma unroll
        for (int s = 0; s < 2; ++s) {
            int q = tid * 2 + s;          // 0..511
            int mm = q >> 2;              // 0..127
            int kk = (q & 3) * 4;
            float4 v = *(const float4*)&S[((size_t)(m_base + mm)) * CCH + kt + kk];
            As[kk + 0][mm] = v.x; As[kk + 1][mm] = v.y;
            As[kk + 2][mm] = v.z; As[kk + 3][mm] = v.w;
        }
        // load B tile (64 rows of Wo x 16 cols), transposed into Bs[k][n]
        {
            int nn = tid >> 2;
            int kk = (tid & 3) * 4;
            float4 v = *(const float4*)&Wo[((size_t)(n_base + nn)) * CCH + kt + kk];
            Bs[kk + 0][nn] = v.x; Bs[kk + 1][nn] = v.y;
            Bs[kk + 2][nn] = v.z; Bs[kk + 3][nn] = v.w;
        }
        __syncthreads();

        #pragma unroll
        for (int k = 0; k < BK; ++k) {
            float4 a0 = *(const float4*)&As[k][ty * 8];
            float4 a1 = *(const float4*)&As[k][ty * 8 + 4];
            float4 bb = *(const float4*)&Bs[k][tx * 4];
            float av[8] = {a0.x, a0.y, a0.z, a0.w, a1.x, a1.y, a1.z, a1.w};
            float bv[4] = {bb.x, bb.y, bb.z, bb.w};
            #pragma unroll
            for (int i = 0; i < 8; ++i)
                #pragma unroll
                for (int j = 0; j < 4; ++j)
                    acc[i][j] += av[i] * bv[j];
        }
        __syncthreads();
    }

    float4 bia = *(const float4*)&bo[n_base + tx * 4];
    #pragma unroll
    for (int i = 0; i < 8; ++i) {
        int m = m_base + ty * 8 + i;
        float4 o = make_float4(acc[i][0] + bia.x, acc[i][1] + bia.y,
                               acc[i][2] + bia.z, acc[i][3] + bia.w);
        *(float4*)&y[(size_t)m * CCH + n_base + tx * 4] = o;
    }
}

// ============================================================================
extern "C" void kernel_launch(void* const* d_in, const int* in_sizes, int n_in,
                              void* d_out, int out_size)
{
    const float* x  = (const float*)d_in[0];
    const float* Wq = (const float*)d_in[1];
    const float* Wk = (const float*)d_in[2];
    const float* Wv = (const float*)d_in[3];
    const float* Wo = (const float*)d_in[4];
    const float* bo = (const float*)d_in[5];
    float* y = (float*)d_out;

    cudaFuncSetAttribute(attn_kernel, cudaFuncAttributeMaxDynamicSharedMemorySize, SMEM_BYTES);

    attn_kernel<<<NWIN * NHEADS, 128, SMEM_BYTES>>>(x, Wq, Wk, Wv);

    dim3 g2(CCH / BN, MROWS / BM);
    proj_kernel<<<g2, 256>>>(Wo, bo, y);
}

// round 2
// speedup vs baseline: 2.3578x; 2.3578x over previous
#include <cuda_runtime.h>
#include <cuda_bf16.h>
#include <math.h>
#include <stdint.h>

#define NHEADS 12
#define DH     64
#define LW     49
#define CCH    768
#define NWIN   2048
#define MROWS  (NWIN * LW)          // 100352

// 308 MB scratch for the concat-head attention output (N, L, C), fp32
__device__ float g_scratch[(size_t)MROWS * CCH];

// ---------------- bf16 plane geometry for the attention kernel -------------
#define ST32  36                    // 32-bit words per row (64 bf16 + pad)
#define STBF  72                    // bf16 elems per row
#define PLANE (64 * STBF)           // bf16 elems per 64-row plane
#define SMEMB (8 * PLANE * 2)       // 8 planes * 2 bytes = 73728 B

// ---------------- helpers ---------------------------------------------------
__device__ __forceinline__ void mma_bf16(float c[4], const uint32_t a[4],
                                         uint32_t b0, uint32_t b1) {
    asm volatile(
        "mma.sync.aligned.m16n8k16.row.col.f32.bf16.bf16.f32 "
        "{%0,%1,%2,%3},{%4,%5,%6,%7},{%8,%9},{%0,%1,%2,%3};\n"
        : "+f"(c[0]), "+f"(c[1]), "+f"(c[2]), "+f"(c[3])
        : "r"(a[0]), "r"(a[1]), "r"(a[2]), "r"(a[3]), "r"(b0), "r"(b1));
}

__device__ __forceinline__ void split_bf(float v, __nv_bfloat16& h, __nv_bfloat16& l) {
    h = __float2bfloat16(v);
    l = __float2bfloat16(v - __bfloat162float(h));
}

__device__ __forceinline__ uint32_t packbf(__nv_bfloat16 a, __nv_bfloat16 b) {
    __nv_bfloat162 t; t.x = a; t.y = b;
    return *reinterpret_cast<uint32_t*>(&t);
}

// ============================================================================
// Kernel A: per-(window, head) fused QKV projection + attention, bf16x3 mma.
// grid = NWIN*NHEADS, 128 threads (4 warps, 2x2 warp grid over 64x64 tiles).
// ============================================================================
__global__ void __launch_bounds__(128)
attn_kernel(const float* __restrict__ x,
            const float* __restrict__ Wq,
            const float* __restrict__ Wk,
            const float* __restrict__ Wv)
{
    extern __shared__ char smraw[];
    __nv_bfloat16* xh = (__nv_bfloat16*)smraw;   // X hi plane [64][72]
    __nv_bfloat16* xl = xh + PLANE;              // X lo
    __nv_bfloat16* Ph = xl + PLANE;              // W hi plane, later P hi
    __nv_bfloat16* Pl = Ph + PLANE;              // W lo plane, later P lo
    __nv_bfloat16* Qh = Pl + PLANE;              // Q hi only
    __nv_bfloat16* Kh = Qh + PLANE;              // K hi only
    __nv_bfloat16* Vh = Kh + PLANE;              // V hi, TRANSPOSED [d][m]
    __nv_bfloat16* Vl = Vh + PLANE;              // V lo, TRANSPOSED
    float* Sc = (float*)smraw;                   // scores fp32 [64][68], alias X planes

    const int tid  = threadIdx.x;
    const int lane = tid & 31;
    const int wid  = tid >> 5;
    const int warp_m = wid >> 1, warp_n = wid & 1;
    const int mbase = warp_m * 32, nbase = warp_n * 32;
    const int lr = lane >> 2;   // 0..7
    const int lc = lane & 3;    // 0..3

    const int h = blockIdx.x % NHEADS;
    const int n = blockIdx.x / NHEADS;
    const int b = n >> 6, hb = (n >> 3) & 7, wb = n & 7;

    // ---- load x window slice for this head, split hi/lo, pad rows = 0 ----
    for (int idx = tid; idx < 4096; idx += 128) {
        int l = idx >> 6, d = idx & 63;
        float v = 0.f;
        if (l < LW) {
            int i = l / 7, j = l - i * 7;
            v = x[(((size_t)(b * 56 + hb * 7 + i)) * 56 + (wb * 7 + j)) * CCH + h * DH + d];
        }
        __nv_bfloat16 hh, ll; split_bf(v, hh, ll);
        xh[l * STBF + d] = hh;
        xl[l * STBF + d] = ll;
    }
    __syncthreads();

    // ---- cache X A-fragments in registers (shared across Q, K, V stages) ----
    uint32_t axh[4][2][4], axl[4][2][4];
    {
        const uint32_t* H = (const uint32_t*)xh;
        const uint32_t* L = (const uint32_t*)xl;
        #pragma unroll
        for (int kc = 0; kc < 4; ++kc)
            #pragma unroll
            for (int f = 0; f < 2; ++f) {
                int w = (mbase + 16 * f + lr) * ST32 + 8 * kc + lc;
                axh[kc][f][0] = H[w];
                axh[kc][f][1] = H[w + 8 * ST32];
                axh[kc][f][2] = H[w + 4];
                axh[kc][f][3] = H[w + 4 + 8 * ST32];
                axl[kc][f][0] = L[w];
                axl[kc][f][1] = L[w + 8 * ST32];
                axl[kc][f][2] = L[w + 4];
                axl[kc][f][3] = L[w + 4 + 8 * ST32];
            }
    }

    // ---- three projections: p=0 Q (hi), p=1 K (hi), p=2 V (hi+lo, transposed)
    const float* Wsrc[3] = {Wq + h * 4096, Wk + h * 4096, Wv + h * 4096};
    for (int p = 0; p < 3; ++p) {
        __syncthreads();   // protect W-plane overwrite
        const float* W = Wsrc[p];
        for (int idx = tid; idx < 4096; idx += 128) {
            int e = idx >> 6, d = idx & 63;
            __nv_bfloat16 hh, ll; split_bf(W[idx], hh, ll);
            Ph[e * STBF + d] = hh;
            Pl[e * STBF + d] = ll;
        }
        __syncthreads();

        float acc[2][4][4] = {};
        #pragma unroll
        for (int pass = 0; pass < 3; ++pass) {
            const uint32_t* B32 = (const uint32_t*)((pass == 1) ? Pl : Ph);
            #pragma unroll
            for (int kc = 0; kc < 4; ++kc)
                #pragma unroll
                for (int g = 0; g < 4; ++g) {
                    int w = (nbase + 8 * g + lr) * ST32 + 8 * kc + lc;
                    uint32_t b0 = B32[w], b1 = B32[w + 4];
                    if (pass < 2) {
                        mma_bf16(acc[0][g], axh[kc][0], b0, b1);
                        mma_bf16(acc[1][g], axh[kc][1], b0, b1);
                    } else {
                        mma_bf16(acc[0][g], axl[kc][0], b0, b1);
                        mma_bf16(acc[1][g], axl[kc][1], b0, b1);
                    }
                }
        }

        if (p < 2) {
            uint32_t* O = (uint32_t*)((p == 0) ? Qh : Kh);
            #pragma unroll
            for (int f = 0; f < 2; ++f)
                #pragma unroll
                for (int g = 0; g < 4; ++g) {
                    int r = mbase + 16 * f + lr;
                    int w = r * ST32 + (nbase + 8 * g) / 2 + lc;
                    O[w] = packbf(__float2bfloat16(acc[f][g][0]),
                                  __float2bfloat16(acc[f][g][1]));
                    O[w + 8 * ST32] = packbf(__float2bfloat16(acc[f][g][2]),
                                             __float2bfloat16(acc[f][g][3]));
                }
        } else {
            #pragma unroll
            for (int f = 0; f < 2; ++f)
                #pragma unroll
                for (int g = 0; g < 4; ++g) {
                    int r  = mbase + 16 * f + lr;
                    int c0 = nbase + 8 * g + 2 * lc;
                    __nv_bfloat16 hh, ll;
                    split_bf(acc[f][g][0], hh, ll);
                    Vh[c0 * STBF + r] = hh;       Vl[c0 * STBF + r] = ll;
                    split_bf(acc[f][g][1], hh, ll);
                    Vh[(c0 + 1) * STBF + r] = hh; Vl[(c0 + 1) * STBF + r] = ll;
                    split_bf(acc[f][g][2], hh, ll);
                    Vh[c0 * STBF + r + 8] = hh;   Vl[c0 * STBF + r + 8] = ll;
                    split_bf(acc[f][g][3], hh, ll);
                    Vh[(c0 + 1) * STBF + r + 8] = hh; Vl[(c0 + 1) * STBF + r + 8] = ll;
                }
        }
    }
    __syncthreads();

    // ---- scores = Qh @ Kh^T (hi-only), scaled + masked, fp32 to Sc ----
    {
        float acc[2][4][4] = {};
        const uint32_t* QA = (const uint32_t*)Qh;
        const uint32_t* KB = (const uint32_t*)Kh;
        #pragma unroll
        for (int kc = 0; kc < 4; ++kc) {
            uint32_t a[2][4];
            #pragma unroll
            for (int f = 0; f < 2; ++f) {
                int w = (mbase + 16 * f + lr) * ST32 + 8 * kc + lc;
                a[f][0] = QA[w];
                a[f][1] = QA[w + 8 * ST32];
                a[f][2] = QA[w + 4];
                a[f][3] = QA[w + 4 + 8 * ST32];
            }
            #pragma unroll
            for (int g = 0; g < 4; ++g) {
                int w = (nbase + 8 * g + lr) * ST32 + 8 * kc + lc;
                uint32_t b0 = KB[w], b1 = KB[w + 4];
                mma_bf16(acc[0][g], a[0], b0, b1);
                mma_bf16(acc[1][g], a[1], b0, b1);
            }
        }
        #pragma unroll
        for (int f = 0; f < 2; ++f)
            #pragma unroll
            for (int g = 0; g < 4; ++g) {
                int r = mbase + 16 * f + lr;
                int c = nbase + 8 * g + 2 * lc;
                Sc[r * 68 + c]           = (c     < LW) ? acc[f][g][0] * 0.125f : -1e30f;
                Sc[r * 68 + c + 1]       = (c + 1 < LW) ? acc[f][g][1] * 0.125f : -1e30f;
                Sc[(r + 8) * 68 + c]     = (c     < LW) ? acc[f][g][2] * 0.125f : -1e30f;
                Sc[(r + 8) * 68 + c + 1] = (c + 1 < LW) ? acc[f][g][3] * 0.125f : -1e30f;
            }
    }
    __syncthreads();

    // ---- softmax rows 0..48 (fp32), write P hi/lo planes (cols>=49 -> 0) ----
    if (tid < LW) {
        float* row = Sc + tid * 68;
        float mx = -1e30f;
        #pragma unroll
        for (int m = 0; m < LW; ++m) mx = fmaxf(mx, row[m]);
        float s = 0.f;
        #pragma unroll
        for (int m = 0; m < LW; ++m) { float e = __expf(row[m] - mx); row[m] = e; s += e; }
        float inv = 1.f / s;
        uint32_t* ph = (uint32_t*)(Ph + tid * STBF);
        uint32_t* pl = (uint32_t*)(Pl + tid * STBF);
        #pragma unroll
        for (int mw = 0; mw < 32; ++mw) {
            int m0 = 2 * mw;
            float p0 = (m0     < LW) ? row[m0] * inv     : 0.f;
            float p1 = (m0 + 1 < LW) ? row[m0 + 1] * inv : 0.f;
            __nv_bfloat16 h0, l0, h1, l1;
            split_bf(p0, h0, l0);
            split_bf(p1, h1, l1);
            ph[mw] = packbf(h0, h1);
            pl[mw] = packbf(l0, l1);
        }
    }
    __syncthreads();

    // ---- out = P @ V (3-term), write fp32 rows < 49 to scratch ----
    {
        float acc[2][4][4] = {};
        #pragma unroll
        for (int pass = 0; pass < 3; ++pass) {
            const uint32_t* A32 = (const uint32_t*)((pass < 2) ? Ph : Pl);
            const uint32_t* B32 = (const uint32_t*)((pass == 1) ? Vl : Vh);
            #pragma unroll
            for (int kc = 0; kc < 4; ++kc) {
                uint32_t a[2][4];
                #pragma unroll
                for (int f = 0; f < 2; ++f) {
                    int w = (mbase + 16 * f + lr) * ST32 + 8 * kc + lc;
                    a[f][0] = A32[w];
                    a[f][1] = A32[w + 8 * ST32];
                    a[f][2] = A32[w + 4];
                    a[f][3] = A32[w + 4 + 8 * ST32];
                }
                #pragma unroll
                for (int g = 0; g < 4; ++g) {
                    int w = (nbase + 8 * g + lr) * ST32 + 8 * kc + lc;
                    uint32_t b0 = B32[w], b1 = B32[w + 4];
                    mma_bf16(acc[0][g], a[0], b0, b1);
                    mma_bf16(acc[1][g], a[1], b0, b1);
                }
            }
        }
        #pragma unroll
        for (int f = 0; f < 2; ++f)
            #pragma unroll
            for (int g = 0; g < 4; ++g) {
                int r = mbase + 16 * f + lr;
                int c = nbase + 8 * g + 2 * lc;
                if (r < LW)
                    *(float2*)&g_scratch[((size_t)n * LW + r) * CCH + h * DH + c] =
                        make_float2(acc[f][g][0], acc[f][g][1]);
                if (r + 8 < LW)
                    *(float2*)&g_scratch[((size_t)n * LW + r + 8) * CCH + h * DH + c] =
                        make_float2(acc[f][g][2], acc[f][g][3]);
            }
    }
}

// ============================================================================
// Kernel B: y = S @ Wo^T + bo, bf16x3 mma GEMM. 128x64x16 tile, 256 threads.
// ============================================================================
#define AST32 12      // 32-bit words per staged row (16 bf16 = 8 words + 4 pad)
#define ASTBF 24

__global__ void __launch_bounds__(256)
proj_kernel(const float* __restrict__ Wo,
            const float* __restrict__ bo,
            float* __restrict__ y)
{
    __shared__ __nv_bfloat16 Ah[128 * ASTBF], Al[128 * ASTBF];
    __shared__ __nv_bfloat16 Bh[64 * ASTBF],  Bl[64 * ASTBF];

    const int tid  = threadIdx.x;
    const int lane = tid & 31;
    const int wid  = tid >> 5;                // 0..7
    const int warp_m = wid >> 1, warp_n = wid & 1;
    const int lr = lane >> 2, lc = lane & 3;
    const int m_base = blockIdx.y * 128;
    const int n_base = blockIdx.x * 64;
    const float* S = g_scratch;

    float acc[2][4][4] = {};

    for (int kt = 0; kt < CCH; kt += 16) {
        __syncthreads();
        // stage A tile (128 x 16), split hi/lo, pack k-pairs
        #pragma unroll
        for (int s = 0; s < 2; ++s) {
            int q = tid * 2 + s;
            int mm = q >> 2, kk = (q & 3) * 4;
            float4 v = *(const float4*)&S[((size_t)(m_base + mm)) * CCH + kt + kk];
            __nv_bfloat16 h0, l0, h1, l1, h2, l2, h3, l3;
            split_bf(v.x, h0, l0); split_bf(v.y, h1, l1);
            split_bf(v.z, h2, l2); split_bf(v.w, h3, l3);
            ((uint32_t*)Ah)[mm * AST32 + kk / 2]     = packbf(h0, h1);
            ((uint32_t*)Ah)[mm * AST32 + kk / 2 + 1] = packbf(h2, h3);
            ((uint32_t*)Al)[mm * AST32 + kk / 2]     = packbf(l0, l1);
            ((uint32_t*)Al)[mm * AST32 + kk / 2 + 1] = packbf(l2, l3);
        }
        // stage B tile (64 x 16) from Wo
        {
            int nn = tid >> 2, kk = (tid & 3) * 4;
            float4 v = *(const float4*)&Wo[((size_t)(n_base + nn)) * CCH + kt + kk];
            __nv_bfloat16 h0, l0, h1, l1, h2, l2, h3, l3;
            split_bf(v.x, h0, l0); split_bf(v.y, h1, l1);
            split_bf(v.z, h2, l2); split_bf(v.w, h3, l3);
            ((uint32_t*)Bh)[nn * AST32 + kk / 2]     = packbf(h0, h1);
            ((uint32_t*)Bh)[nn * AST32 + kk / 2 + 1] = packbf(h2, h3);
            ((uint32_t*)Bl)[nn * AST32 + kk / 2]     = packbf(l0, l1);
            ((uint32_t*)Bl)[nn * AST32 + kk / 2 + 1] = packbf(l2, l3);
        }
        __syncthreads();

        uint32_t a_h[2][4], a_l[2][4];
        #pragma unroll
        for (int f = 0; f < 2; ++f) {
            int w = (warp_m * 32 + 16 * f + lr) * AST32 + lc;
            a_h[f][0] = ((const uint32_t*)Ah)[w];
            a_h[f][1] = ((const uint32_t*)Ah)[w + 8 * AST32];
            a_h[f][2] = ((const uint32_t*)Ah)[w + 4];
            a_h[f][3] = ((const uint32_t*)Ah)[w + 4 + 8 * AST32];
            a_l[f][0] = ((const uint32_t*)Al)[w];
            a_l[f][1] = ((const uint32_t*)Al)[w + 8 * AST32];
            a_l[f][2] = ((const uint32_t*)Al)[w + 4];
            a_l[f][3] = ((const uint32_t*)Al)[w + 4 + 8 * AST32];
        }
        #pragma unroll
        for (int g = 0; g < 4; ++g) {
            int w = (warp_n * 32 + 8 * g + lr) * AST32 + lc;
            uint32_t bh0 = ((const uint32_t*)Bh)[w], bh1 = ((const uint32_t*)Bh)[w + 4];
            uint32_t bl0 = ((const uint32_t*)Bl)[w], bl1 = ((const uint32_t*)Bl)[w + 4];
            #pragma unroll
            for (int f = 0; f < 2; ++f) {
                mma_bf16(acc[f][g], a_h[f], bh0, bh1);
                mma_bf16(acc[f][g], a_h[f], bl0, bl1);
                mma_bf16(acc[f][g], a_l[f], bh0, bh1);
            }
        }
    }

    // epilogue: bias + store
    #pragma unroll
    for (int g = 0; g < 4; ++g) {
        int c = n_base + warp_n * 32 + 8 * g + 2 * lc;
        float b0 = bo[c], b1 = bo[c + 1];
        #pragma unroll
        for (int f = 0; f < 2; ++f) {
            int r = m_base + warp_m * 32 + 16 * f + lr;
            *(float2*)&y[(size_t)r * CCH + c] =
                make_float2(acc[f][g][0] + b0, acc[f][g][1] + b1);
            *(float2*)&y[(size_t)(r + 8) * CCH + c] =
                make_float2(acc[f][g][2] + b0, acc[f][g][3] + b1);
        }
    }
}

// ============================================================================
extern "C" void kernel_launch(void* const* d_in, const int* in_sizes, int n_in,
                              void* d_out, int out_size)
{
    const float* x  = (const float*)d_in[0];
    const float* Wq = (const float*)d_in[1];
    const float* Wk = (const float*)d_in[2];
    const float* Wv = (const float*)d_in[3];
    const float* Wo = (const float*)d_in[4];
    const float* bo = (const float*)d_in[5];
    float* y = (float*)d_out;

    cudaFuncSetAttribute(attn_kernel, cudaFuncAttributeMaxDynamicSharedMemorySize, SMEMB);

    attn_kernel<<<NWIN * NHEADS, 128, SMEMB>>>(x, Wq, Wk, Wv);

    dim3 g2(CCH / 64, MROWS / 128);
    proj_kernel<<<g2, 256>>>(Wo, bo, y);
}

// round 3
// speedup vs baseline: 3.7260x; 1.5803x over previous
#include <cuda_runtime.h>
#include <cuda_bf16.h>
#include <stdint.h>
#include <math.h>

#define NHEADS 12
#define DH     64
#define LW     49
#define CCH    768
#define NWIN   2048
#define MROWS  (NWIN * LW)                 // 100352
#define XTOT   ((size_t)MROWS * CCH)       // 77,070,336 elements

// ---------------- device-global split planes -------------------------------
__device__ __nv_bfloat16 g_xh[(size_t)MROWS * CCH];
__device__ __nv_bfloat16 g_xl[(size_t)MROWS * CCH];
__device__ __nv_bfloat16 g_sh[(size_t)MROWS * CCH];   // attention out hi
__device__ __nv_bfloat16 g_sl[(size_t)MROWS * CCH];   // attention out lo
__device__ __nv_bfloat16 g_wqh[12 * 4096], g_wkh[12 * 4096];
__device__ __nv_bfloat16 g_wvh[12 * 4096], g_wvl[12 * 4096];
__device__ __nv_bfloat16 g_woh[589824], g_wol[589824];

// ---------------- helpers ---------------------------------------------------
__device__ __forceinline__ void mma_bf16(float c[4], const uint32_t a[4],
                                         uint32_t b0, uint32_t b1) {
    asm volatile(
        "mma.sync.aligned.m16n8k16.row.col.f32.bf16.bf16.f32 "
        "{%0,%1,%2,%3},{%4,%5,%6,%7},{%8,%9},{%0,%1,%2,%3};\n"
        : "+f"(c[0]), "+f"(c[1]), "+f"(c[2]), "+f"(c[3])
        : "r"(a[0]), "r"(a[1]), "r"(a[2]), "r"(a[3]), "r"(b0), "r"(b1));
}

__device__ __forceinline__ void ldsm4(uint32_t r[4], uint32_t saddr) {
    asm volatile("ldmatrix.sync.aligned.m8n8.x4.shared.b16 {%0,%1,%2,%3},[%4];"
                 : "=r"(r[0]), "=r"(r[1]), "=r"(r[2]), "=r"(r[3]) : "r"(saddr));
}

__device__ __forceinline__ void split_bf(float v, __nv_bfloat16& h, __nv_bfloat16& l) {
    h = __float2bfloat16(v);
    l = __float2bfloat16(v - __bfloat162float(h));
}

__device__ __forceinline__ uint32_t packbf(__nv_bfloat16 a, __nv_bfloat16 b) {
    __nv_bfloat162 t; t.x = a; t.y = b;
    return *reinterpret_cast<uint32_t*>(&t);
}

__device__ __forceinline__ void cpa16(uint32_t dst, const void* src) {
    asm volatile("cp.async.cg.shared.global [%0], [%1], 16;" :: "r"(dst), "l"(src));
}
__device__ __forceinline__ void cpa_commit() { asm volatile("cp.async.commit_group;"); }
template<int N> __device__ __forceinline__ void cpa_wait() {
    asm volatile("cp.async.wait_group %0;" :: "n"(N));
}

// ============================================================================
// Prep kernels: one-time fp32 -> split bf16 conversions
// ============================================================================
__global__ void split_x_kernel(const float* __restrict__ x) {
    size_t np = XTOT / 2;
    for (size_t i = blockIdx.x * (size_t)blockDim.x + threadIdx.x; i < np;
         i += (size_t)gridDim.x * blockDim.x) {
        float2 v = ((const float2*)x)[i];
        __nv_bfloat16 h0, l0, h1, l1;
        split_bf(v.x, h0, l0); split_bf(v.y, h1, l1);
        ((uint32_t*)g_xh)[i] = packbf(h0, h1);
        ((uint32_t*)g_xl)[i] = packbf(l0, l1);
    }
}

__global__ void split_w_kernel(const float* __restrict__ Wq, const float* __restrict__ Wk,
                               const float* __restrict__ Wv, const float* __restrict__ Wo) {
    int np = 589824 / 2;
    for (int i = blockIdx.x * blockDim.x + threadIdx.x; i < np;
         i += gridDim.x * blockDim.x) {
        float2 v = ((const float2*)Wo)[i];
        __nv_bfloat16 h0, l0, h1, l1;
        split_bf(v.x, h0, l0); split_bf(v.y, h1, l1);
        ((uint32_t*)g_woh)[i] = packbf(h0, h1);
        ((uint32_t*)g_wol)[i] = packbf(l0, l1);
        if (i < 24576) {
            float2 q = ((const float2*)Wq)[i];
            ((uint32_t*)g_wqh)[i] = packbf(__float2bfloat16(q.x), __float2bfloat16(q.y));
            float2 k = ((const float2*)Wk)[i];
            ((uint32_t*)g_wkh)[i] = packbf(__float2bfloat16(k.x), __float2bfloat16(k.y));
            float2 w = ((const float2*)Wv)[i];
            split_bf(w.x, h0, l0); split_bf(w.y, h1, l1);
            ((uint32_t*)g_wvh)[i] = packbf(h0, h1);
            ((uint32_t*)g_wvl)[i] = packbf(l0, l1);
        }
    }
}

// ============================================================================
// Kernel A: per-(window, head) fused QKV projection + attention.
// 128 threads (4 warps, 2x2 warp grid over 64x64 padded tiles), ldmatrix+mma.
// ============================================================================
#define STBF  72
#define PLANE (64 * STBF)
#define PLB   (PLANE * 2)              // plane size in bytes = 9216
#define SMEMB (8 * PLB)                // 73728

// one 64x64x64 bf16 GEMM pass, acc += A(64x64 row-major) * B(64x64 col-major)
__device__ __forceinline__ void gemm_pass(float acc[2][4][4], uint32_t aBase,
                                          uint32_t bBase, int mbase, int nbase,
                                          int lane) {
    const int r16 = lane & 15;
    const uint32_t kaq = (lane >> 4) * 16;
    #pragma unroll
    for (int kc = 0; kc < 4; ++kc) {
        uint32_t ka = kaq + kc * 32;
        uint32_t a0[4], a1[4], b0[4], b1[4];
        ldsm4(a0, aBase + (mbase + r16) * 144 + ka);
        ldsm4(a1, aBase + (mbase + 16 + r16) * 144 + ka);
        ldsm4(b0, bBase + (nbase + r16) * 144 + ka);
        ldsm4(b1, bBase + (nbase + 16 + r16) * 144 + ka);
        mma_bf16(acc[0][0], a0, b0[0], b0[2]);
        mma_bf16(acc[0][1], a0, b0[1], b0[3]);
        mma_bf16(acc[0][2], a0, b1[0], b1[2]);
        mma_bf16(acc[0][3], a0, b1[1], b1[3]);
        mma_bf16(acc[1][0], a1, b0[0], b0[2]);
        mma_bf16(acc[1][1], a1, b0[1], b0[3]);
        mma_bf16(acc[1][2], a1, b1[0], b1[2]);
        mma_bf16(acc[1][3], a1, b1[1], b1[3]);
    }
}

__global__ void __launch_bounds__(128, 3)
attn_kernel()
{
    extern __shared__ __nv_bfloat16 sm[];
    __nv_bfloat16* xh = sm;                 // later aliased by Sc (fp32 scores)
    __nv_bfloat16* xl = sm + PLANE;
    __nv_bfloat16* Wh = sm + 2 * PLANE;     // later P hi
    __nv_bfloat16* Wl = sm + 3 * PLANE;     // later P lo
    __nv_bfloat16* Qh = sm + 4 * PLANE;
    __nv_bfloat16* Kh = sm + 5 * PLANE;
    __nv_bfloat16* Vh = sm + 6 * PLANE;     // V transposed [d][m]
    __nv_bfloat16* Vl = sm + 7 * PLANE;
    float* Sc = (float*)sm;                 // [64][68] fp32, 17408 B

    const int tid = threadIdx.x, lane = tid & 31, wid = tid >> 5;
    const int warp_m = wid >> 1, warp_n = wid & 1;
    const int mbase = warp_m * 32, nbase = warp_n * 32;
    const int lr = lane >> 2, lc = lane & 3;

    const int h = blockIdx.x % NHEADS;
    const int n = blockIdx.x / NHEADS;
    const int b = n >> 6, hb = (n >> 3) & 7, wb = n & 7;

    const uint32_t sb = (uint32_t)__cvta_generic_to_shared(sm);
    const uint32_t sXH = sb, sXL = sb + PLB, sWH = sb + 2 * PLB, sWL = sb + 3 * PLB;
    const uint32_t sQH = sb + 4 * PLB, sKH = sb + 5 * PLB;
    const uint32_t sVH = sb + 6 * PLB, sVL = sb + 7 * PLB;

    // ---- stage x planes (bf16 gmem -> smem, uint4), pad rows zero ----
    for (int q = tid; q < 1024; q += 128) {
        int p = q >> 9, rem = q & 511, l = rem >> 3, ch = rem & 7;
        uint4 v = make_uint4(0, 0, 0, 0);
        if (l < LW) {
            int i = l / 7, j = l - i * 7;
            size_t off = (((size_t)(b * 56 + hb * 7 + i)) * 56 + (wb * 7 + j)) * CCH
                         + h * DH + ch * 8;
            v = *(const uint4*)((p ? g_xl : g_xh) + off);
        }
        *(uint4*)((p ? xl : xh) + l * STBF + ch * 8) = v;
    }
    // stage Wq (hi only)
    for (int q = tid; q < 512; q += 128) {
        int e = q >> 3, ch = q & 7;
        *(uint4*)(Wh + e * STBF + ch * 8) = *(const uint4*)(g_wqh + h * 4096 + e * 64 + ch * 8);
    }
    __syncthreads();

    // ---- Q = xh @ Wqh (1 pass) ----
    {
        float acc[2][4][4] = {};
        gemm_pass(acc, sXH, sWH, mbase, nbase, lane);
        uint32_t* O = (uint32_t*)Qh;
        #pragma unroll
        for (int f = 0; f < 2; ++f)
            #pragma unroll
            for (int g = 0; g < 4; ++g) {
                int r = mbase + 16 * f + lr;
                int w = r * 36 + (nbase + 8 * g) / 2 + lc;
                O[w] = packbf(__float2bfloat16(acc[f][g][0]), __float2bfloat16(acc[f][g][1]));
                O[w + 8 * 36] = packbf(__float2bfloat16(acc[f][g][2]), __float2bfloat16(acc[f][g][3]));
            }
    }
    __syncthreads();

    // ---- K = xh @ Wkh (1 pass) ----
    for (int q = tid; q < 512; q += 128) {
        int e = q >> 3, ch = q & 7;
        *(uint4*)(Wh + e * STBF + ch * 8) = *(const uint4*)(g_wkh + h * 4096 + e * 64 + ch * 8);
    }
    __syncthreads();
    {
        float acc[2][4][4] = {};
        gemm_pass(acc, sXH, sWH, mbase, nbase, lane);
        uint32_t* O = (uint32_t*)Kh;
        #pragma unroll
        for (int f = 0; f < 2; ++f)
            #pragma unroll
            for (int g = 0; g < 4; ++g) {
                int r = mbase + 16 * f + lr;
                int w = r * 36 + (nbase + 8 * g) / 2 + lc;
                O[w] = packbf(__float2bfloat16(acc[f][g][0]), __float2bfloat16(acc[f][g][1]));
                O[w + 8 * 36] = packbf(__float2bfloat16(acc[f][g][2]), __float2bfloat16(acc[f][g][3]));
            }
    }
    __syncthreads();

    // ---- V = x @ Wv (3-term split), stored transposed hi/lo ----
    for (int q = tid; q < 1024; q += 128) {
        int p = q >> 9, rem = q & 511, e = rem >> 3, ch = rem & 7;
        *(uint4*)((p ? Wl : Wh) + e * STBF + ch * 8) =
            *(const uint4*)((p ? g_wvl : g_wvh) + h * 4096 + e * 64 + ch * 8);
    }
    __syncthreads();
    {
        float acc[2][4][4] = {};
        gemm_pass(acc, sXH, sWH, mbase, nbase, lane);
        gemm_pass(acc, sXH, sWL, mbase, nbase, lane);
        gemm_pass(acc, sXL, sWH, mbase, nbase, lane);
        #pragma unroll
        for (int f = 0; f < 2; ++f)
            #pragma unroll
            for (int g = 0; g < 4; ++g) {
                int r = mbase + 16 * f + lr;
                int c0 = nbase + 8 * g + 2 * lc;
                __nv_bfloat16 hh, ll;
                split_bf(acc[f][g][0], hh, ll);
                Vh[c0 * STBF + r] = hh;           Vl[c0 * STBF + r] = ll;
                split_bf(acc[f][g][1], hh, ll);
                Vh[(c0 + 1) * STBF + r] = hh;     Vl[(c0 + 1) * STBF + r] = ll;
                split_bf(acc[f][g][2], hh, ll);
                Vh[c0 * STBF + r + 8] = hh;       Vl[c0 * STBF + r + 8] = ll;
                split_bf(acc[f][g][3], hh, ll);
                Vh[(c0 + 1) * STBF + r + 8] = hh; Vl[(c0 + 1) * STBF + r + 8] = ll;
            }
    }
    __syncthreads();

    // ---- scores = Qh @ Kh^T, scale + mask -> Sc (aliases x planes) ----
    {
        float acc[2][4][4] = {};
        gemm_pass(acc, sQH, sKH, mbase, nbase, lane);
        #pragma unroll
        for (int f = 0; f < 2; ++f)
            #pragma unroll
            for (int g = 0; g < 4; ++g) {
                int r = mbase + 16 * f + lr;
                int c = nbase + 8 * g + 2 * lc;
                Sc[r * 68 + c]           = (c     < LW) ? acc[f][g][0] * 0.125f : -1e30f;
                Sc[r * 68 + c + 1]       = (c + 1 < LW) ? acc[f][g][1] * 0.125f : -1e30f;
                Sc[(r + 8) * 68 + c]     = (c     < LW) ? acc[f][g][2] * 0.125f : -1e30f;
                Sc[(r + 8) * 68 + c + 1] = (c + 1 < LW) ? acc[f][g][3] * 0.125f : -1e30f;
            }
    }
    __syncthreads();

    // ---- softmax rows 0..48, write P hi/lo (aliases W planes) ----
    if (tid < LW) {
        float* row = Sc + tid * 68;
        float mx = -1e30f;
        #pragma unroll
        for (int m = 0; m < LW; ++m) mx = fmaxf(mx, row[m]);
        float s = 0.f;
        #pragma unroll
        for (int m = 0; m < LW; ++m) { float e = __expf(row[m] - mx); row[m] = e; s += e; }
        float inv = 1.f / s;
        uint32_t* ph = (uint32_t*)(Wh + tid * STBF);
        uint32_t* pl = (uint32_t*)(Wl + tid * STBF);
        #pragma unroll
        for (int mw = 0; mw < 32; ++mw) {
            int m0 = 2 * mw;
            float p0 = (m0     < LW) ? row[m0] * inv     : 0.f;
            float p1 = (m0 + 1 < LW) ? row[m0 + 1] * inv : 0.f;
            __nv_bfloat16 h0, l0, h1, l1;
            split_bf(p0, h0, l0);
            split_bf(p1, h1, l1);
            ph[mw] = packbf(h0, h1);
            pl[mw] = packbf(l0, l1);
        }
    }
    __syncthreads();

    // ---- out = P @ V (3-term), store split bf16 to g_sh/g_sl ----
    {
        float acc[2][4][4] = {};
        gemm_pass(acc, sWH, sVH, mbase, nbase, lane);
        gemm_pass(acc, sWH, sVL, mbase, nbase, lane);
        gemm_pass(acc, sWL, sVH, mbase, nbase, lane);
        #pragma unroll
        for (int f = 0; f < 2; ++f)
            #pragma unroll
            for (int g = 0; g < 4; ++g) {
                int r = mbase + 16 * f + lr;
                int c = nbase + 8 * g + 2 * lc;
                __nv_bfloat16 h0, l0, h1, l1;
                if (r < LW) {
                    size_t off = ((size_t)n * LW + r) * CCH + h * DH + c;
                    split_bf(acc[f][g][0], h0, l0);
                    split_bf(acc[f][g][1], h1, l1);
                    *(uint32_t*)(g_sh + off) = packbf(h0, h1);
                    *(uint32_t*)(g_sl + off) = packbf(l0, l1);
                }
                if (r + 8 < LW) {
                    size_t off = ((size_t)n * LW + r + 8) * CCH + h * DH + c;
                    split_bf(acc[f][g][2], h0, l0);
                    split_bf(acc[f][g][3], h1, l1);
                    *(uint32_t*)(g_sh + off) = packbf(h0, h1);
                    *(uint32_t*)(g_sl + off) = packbf(l0, l1);
                }
            }
    }
}

// ============================================================================
// Kernel B: y = S @ Wo^T + bo, bf16x3, cp.async double-buffered, ldmatrix.
// Block 128x64, BK=32, 256 threads (8 warps, 4x2 grid of 32x32 warp tiles).
// ============================================================================
#define PST 40                         // bf16 stride of staged rows (80 B)
#define OAH(s) ((s) * 5120)
#define OAL(s) (10240 + (s) * 5120)
#define OBH(s) (20480 + (s) * 2560)
#define OBL(s) (25600 + (s) * 2560)
#define PSMEM  (30720 * 2)             // 61440 B

__global__ void __launch_bounds__(256, 2)
proj_kernel(const float* __restrict__ bo, float* __restrict__ y)
{
    extern __shared__ __nv_bfloat16 psm[];
    const int tid = threadIdx.x, lane = tid & 31, wid = tid >> 5;
    const int warp_m = wid >> 1, warp_n = wid & 1;
    const int lr = lane >> 2, lc = lane & 3;
    const int m_base = blockIdx.y * 128, n_base = blockIdx.x * 64;
    const uint32_t sb = (uint32_t)__cvta_generic_to_shared(psm);
    const int r16 = lane & 15;
    const uint32_t kaq = (lane >> 4) * 16;

    float acc[2][4][4] = {};

    auto stage = [&](int s, int kt) {
        for (int c = tid; c < 1024; c += 256) {
            int p = c >> 9, rem = c & 511, row = rem >> 2, ch = rem & 3;
            const __nv_bfloat16* src =
                (p ? g_sl : g_sh) + (size_t)(m_base + row) * CCH + kt + ch * 8;
            cpa16(sb + ((p ? OAL(s) : OAH(s)) + row * PST + ch * 8) * 2, src);
        }
        for (int c = tid; c < 512; c += 256) {
            int p = c >> 8, rem = c & 255, row = rem >> 2, ch = rem & 3;
            const __nv_bfloat16* src =
                (p ? g_wol : g_woh) + (size_t)(n_base + row) * CCH + kt + ch * 8;
            cpa16(sb + ((p ? OBL(s) : OBH(s)) + row * PST + ch * 8) * 2, src);
        }
        cpa_commit();
    };

    auto compute = [&](int s) {
        const uint32_t aH = sb + OAH(s) * 2, aL = sb + OAL(s) * 2;
        const uint32_t bH = sb + OBH(s) * 2, bL = sb + OBL(s) * 2;
        #pragma unroll
        for (int kc = 0; kc < 2; ++kc) {
            uint32_t ka = kaq + kc * 32;
            uint32_t ah0[4], ah1[4], al0[4], al1[4], bh0[4], bh1[4], bl0[4], bl1[4];
            ldsm4(ah0, aH + (warp_m * 32 + r16) * 80 + ka);
            ldsm4(ah1, aH + (warp_m * 32 + 16 + r16) * 80 + ka);
            ldsm4(al0, aL + (warp_m * 32 + r16) * 80 + ka);
            ldsm4(al1, aL + (warp_m * 32 + 16 + r16) * 80 + ka);
            ldsm4(bh0, bH + (warp_n * 32 + r16) * 80 + ka);
            ldsm4(bh1, bH + (warp_n * 32 + 16 + r16) * 80 + ka);
            ldsm4(bl0, bL + (warp_n * 32 + r16) * 80 + ka);
            ldsm4(bl1, bL + (warp_n * 32 + 16 + r16) * 80 + ka);
            // g0,g1 from (bh0/bl0); g2,g3 from (bh1/bl1)
            mma_bf16(acc[0][0], ah0, bh0[0], bh0[2]);
            mma_bf16(acc[0][0], ah0, bl0[0], bl0[2]);
            mma_bf16(acc[0][0], al0, bh0[0], bh0[2]);
            mma_bf16(acc[0][1], ah0, bh0[1], bh0[3]);
            mma_bf16(acc[0][1], ah0, bl0[1], bl0[3]);
            mma_bf16(acc[0][1], al0, bh0[1], bh0[3]);
            mma_bf16(acc[0][2], ah0, bh1[0], bh1[2]);
            mma_bf16(acc[0][2], ah0, bl1[0], bl1[2]);
            mma_bf16(acc[0][2], al0, bh1[0], bh1[2]);
            mma_bf16(acc[0][3], ah0, bh1[1], bh1[3]);
            mma_bf16(acc[0][3], ah0, bl1[1], bl1[3]);
            mma_bf16(acc[0][3], al0, bh1[1], bh1[3]);
            mma_bf16(acc[1][0], ah1, bh0[0], bh0[2]);
            mma_bf16(acc[1][0], ah1, bl0[0], bl0[2]);
            mma_bf16(acc[1][0], al1, bh0[0], bh0[2]);
            mma_bf16(acc[1][1], ah1, bh0[1], bh0[3]);
            mma_bf16(acc[1][1], ah1, bl0[1], bl0[3]);
            mma_bf16(acc[1][1], al1, bh0[1], bh0[3]);
            mma_bf16(acc[1][2], ah1, bh1[0], bh1[2]);
            mma_bf16(acc[1][2], ah1, bl1[0], bl1[2]);
            mma_bf16(acc[1][2], al1, bh1[0], bh1[2]);
            mma_bf16(acc[1][3], ah1, bh1[1], bh1[3]);
            mma_bf16(acc[1][3], ah1, bl1[1], bl1[3]);
            mma_bf16(acc[1][3], al1, bh1[1], bh1[3]);
        }
    };

    stage(0, 0);
    #pragma unroll 1
    for (int t = 0; t < 24; ++t) {
        if (t + 1 < 24) { stage((t + 1) & 1, (t + 1) * 32); cpa_wait<1>(); }
        else            { cpa_wait<0>(); }
        __syncthreads();
        compute(t & 1);
        __syncthreads();
    }

    // epilogue: bias + fp32 store
    #pragma unroll
    for (int g = 0; g < 4; ++g) {
        int c = n_base + warp_n * 32 + 8 * g + 2 * lc;
        float b0 = bo[c], b1 = bo[c + 1];
        #pragma unroll
        for (int f = 0; f < 2; ++f) {
            int r = m_base + warp_m * 32 + 16 * f + lr;
            *(float2*)&y[(size_t)r * CCH + c] =
                make_float2(acc[f][g][0] + b0, acc[f][g][1] + b1);
            *(float2*)&y[(size_t)(r + 8) * CCH + c] =
                make_float2(acc[f][g][2] + b0, acc[f][g][3] + b1);
        }
    }
}

// ============================================================================
extern "C" void kernel_launch(void* const* d_in, const int* in_sizes, int n_in,
                              void* d_out, int out_size)
{
    const float* x  = (const float*)d_in[0];
    const float* Wq = (const float*)d_in[1];
    const float* Wk = (const float*)d_in[2];
    const float* Wv = (const float*)d_in[3];
    const float* Wo = (const float*)d_in[4];
    const float* bo = (const float*)d_in[5];
    float* y = (float*)d_out;

    cudaFuncSetAttribute(attn_kernel, cudaFuncAttributeMaxDynamicSharedMemorySize, SMEMB);
    cudaFuncSetAttribute(proj_kernel, cudaFuncAttributeMaxDynamicSharedMemorySize, PSMEM);

    split_x_kernel<<<2048, 256>>>(x);
    split_w_kernel<<<576, 256>>>(Wq, Wk, Wv, Wo);
    attn_kernel<<<NWIN * NHEADS, 128, SMEMB>>>();
    proj_kernel<<<dim3(CCH / 64, MROWS / 128), 256, PSMEM>>>(bo, y);
}